// round 11
// baseline (speedup 1.0000x reference)
#include <cuda_runtime.h>

#define BB 16
#define NN 2048
#define NCTX 2047
#define EMB 64
#define DIN 160
#define NLAYERS 3
#define CHN 64
#define ACH 32
#define CC 128

typedef unsigned long long ull;

#define PACK2(d, x)      asm("mov.b64 %0, {%1, %1};" : "=l"(d) : "f"(x))
#define UNPACK2(lo, hi, v) asm("mov.b64 {%0, %1}, %2;" : "=f"(lo), "=f"(hi) : "l"(v))
#define FMA2(d, a, b, c) asm("fma.rn.f32x2 %0, %1, %2, %3;" : "=l"(d) : "l"(a), "l"(b), "l"(c))

// Scratch (allocation-free rule: device globals)
__device__ float g_R[BB * 96 * 32];   // accumulated R per batch
__device__ float g_P[BB * 64 * 32];   // P[c][j] per batch

// ---------------- Kernel Z: zero g_R ----------------
extern "C" __global__ void kZ() {
    int i = blockIdx.x * 256 + threadIdx.x;
    if (i < BB * 3072) g_R[i] = 0.f;
}

// ---------------- Kernel A: R[b] += x[0:96,chunk] @ x[0:32,chunk]^T ----------------
// 256 threads, 3 row-pairs x 2 cols per thread, transposed tile sx[n][96] stride 98.
extern "C" __global__ void __launch_bounds__(256) kA(const float* __restrict__ x) {
    __shared__ float sx[CHN * 98];
    const int b = blockIdx.y, ch = blockIdx.x, tid = threadIdx.x;
    const int n0 = ch * CHN;
    const int count = min(CHN, NCTX - n0);
    const float* xb = x + (size_t)b * DIN * NN;
    for (int i = tid; i < 96 * CHN; i += 256) {
        int r = i >> 6, n = i & 63;
        sx[n * 98 + r] = (n < count) ? xb[r * NN + n0 + n] : 0.f;
    }
    __syncthreads();
    const int tc = tid & 15, tr = tid >> 4;   // tr 0..15
    const int r0 = tr * 6, j0 = tc * 2;
    ull acc[3][2];
#pragma unroll
    for (int p = 0; p < 3; p++) { acc[p][0] = 0ull; acc[p][1] = 0ull; }
#pragma unroll 4
    for (int n = 0; n < CHN; n++) {
        const float* row = sx + n * 98;
        ull a0 = *(const ull*)(row + r0);       // rows r0, r0+1
        ull a1 = *(const ull*)(row + r0 + 2);
        ull a2 = *(const ull*)(row + r0 + 4);
        float2 q = *(const float2*)(row + j0);  // xq cols j0, j0+1
        ull q0, q1;
        PACK2(q0, q.x); PACK2(q1, q.y);
        FMA2(acc[0][0], a0, q0, acc[0][0]); FMA2(acc[0][1], a0, q1, acc[0][1]);
        FMA2(acc[1][0], a1, q0, acc[1][0]); FMA2(acc[1][1], a1, q1, acc[1][1]);
        FMA2(acc[2][0], a2, q0, acc[2][0]); FMA2(acc[2][1], a2, q1, acc[2][1]);
    }
    float* rb = g_R + b * 3072;
#pragma unroll
    for (int p = 0; p < 3; p++) {
#pragma unroll
        for (int c = 0; c < 2; c++) {
            float lo, hi;
            UNPACK2(lo, hi, acc[p][c]);
            atomicAdd(rb + (r0 + 2 * p) * 32 + j0 + c, lo);
            atomicAdd(rb + (r0 + 2 * p + 1) * 32 + j0 + c, hi);
        }
    }
}

// ---------------- Kernel B: per-batch tiny algebra -> P ----------------
extern "C" __global__ void kB(const float* __restrict__ alpha,
                              const float* __restrict__ kp_,
                              const float* __restrict__ E,
                              const float* __restrict__ M) {
    extern __shared__ float smb[];
    float* sE   = smb;           // 4096
    float* sM   = sE + 4096;     // 4096
    float* sR   = sM + 4096;     // 3072  (rows 0..31 = G, rows 32..95 = C)
    float* sW   = sR + 3072;     // 2048
    float* sS   = sW + 2048;     // 2048
    float* sT   = sS + 2048;     // 2048
    float* sSum = sT + 2048;     // 2048
    const int b = blockIdx.x, tid = threadIdx.x; // 512 threads
    for (int i = tid; i < 4096; i += 512) { sE[i] = E[i]; sM[i] = M[i]; }
    for (int i = tid; i < 3072; i += 512) sR[i] = g_R[b * 3072 + i];
    for (int i = tid; i < 2048; i += 512) sSum[i] = 0.f;
    __syncthreads();

    const int i0 = tid >> 3;
    const int j0 = (tid & 7) * 4;
    const float* sC = sR + 32 * 32;

    // W0 = E @ C
    {
        float a0 = 0, a1 = 0, a2 = 0, a3 = 0;
#pragma unroll
        for (int k = 0; k < 64; k++) {
            float e = sE[i0 * 64 + k];
            float4 cv = *(const float4*)(sC + k * 32 + j0);
            a0 += e * cv.x; a1 += e * cv.y; a2 += e * cv.z; a3 += e * cv.w;
        }
        *(float4*)(sW + i0 * 32 + j0) = make_float4(a0, a1, a2, a3);
    }
    __syncthreads();

    const float kp = kp_[0];
    for (int l = 0; l < NLAYERS; l++) {
        float sc = kp * alpha[l * EMB + i0] * (1.0f / (float)NCTX);
        {
            float4 wv = *(const float4*)(sW + i0 * 32 + j0);
            float4 sv = make_float4(sc * wv.x, sc * wv.y, sc * wv.z, sc * wv.w);
            *(float4*)(sS + i0 * 32 + j0) = sv;
            float4 su = *(const float4*)(sSum + i0 * 32 + j0);
            su.x += sv.x; su.y += sv.y; su.z += sv.z; su.w += sv.w;
            *(float4*)(sSum + i0 * 32 + j0) = su;
        }
        __syncthreads();
        if (l < NLAYERS - 1) {
            // T = M @ S
            float a0 = 0, a1 = 0, a2 = 0, a3 = 0;
#pragma unroll
            for (int k = 0; k < 64; k++) {
                float m = sM[i0 * 64 + k];
                float4 sv = *(const float4*)(sS + k * 32 + j0);
                a0 += m * sv.x; a1 += m * sv.y; a2 += m * sv.z; a3 += m * sv.w;
            }
            *(float4*)(sT + i0 * 32 + j0) = make_float4(a0, a1, a2, a3);
            __syncthreads();
            // W += T @ G
            a0 = 0; a1 = 0; a2 = 0; a3 = 0;
#pragma unroll
            for (int p = 0; p < 32; p++) {
                float t = sT[i0 * 32 + p];
                float4 gv = *(const float4*)(sR + p * 32 + j0);
                a0 += t * gv.x; a1 += t * gv.y; a2 += t * gv.z; a3 += t * gv.w;
            }
            float4 wv = *(const float4*)(sW + i0 * 32 + j0);
            wv.x += a0; wv.y += a1; wv.z += a2; wv.w += a3;
            *(float4*)(sW + i0 * 32 + j0) = wv;
            __syncthreads();
        }
    }
    // P[c][j] = sum_d E[d][c] * Sum[d][j]  (c = i0)
    {
        float a0 = 0, a1 = 0, a2 = 0, a3 = 0;
#pragma unroll
        for (int d = 0; d < 64; d++) {
            float e = sE[d * 64 + i0];
            float4 sv = *(const float4*)(sSum + d * 32 + j0);
            a0 += e * sv.x; a1 += e * sv.y; a2 += e * sv.z; a3 += e * sv.w;
        }
        *(float4*)(g_P + (size_t)(b * 64 + i0) * 32 + j0) = make_float4(a0, a1, a2, a3);
    }
}

// ---------------- Kernel C: logits = U^T @ V, class-pair f32x2 tiles ----------------
// CC=128 cols/CTA, 256 threads, 8 classes x 4 cols per thread; u pairs are native
// ulonglong2 loads from sU (classes adjacent), only v is PACKed (4 per 64 MACs).
extern "C" __global__ void __launch_bounds__(256) kC(const float* __restrict__ x,
                                                     const float* __restrict__ E,
                                                     float* __restrict__ out) {
    extern __shared__ float smc[];
    float* sU = smc;            // 96 x 64
    float* sV = sU + 96 * 64;   // 96 x 128
    const int b = blockIdx.y, chn = blockIdx.x, tid = threadIdx.x;
    const int n0 = chn * CC;
    const float* xb = x + (size_t)b * DIN * NN;
    // U[k][c]: k<64 -> E[k][c]; k=64+j -> P[c][j]
    for (int i = tid; i < 96 * 64; i += 256) {
        int k = i >> 6, c = i & 63;
        sU[i] = (k < 64) ? E[i] : g_P[(size_t)(b * 64 + c) * 32 + (k - 64)];
    }
    // V[k][n]: k<64 -> f0 row (96+k); k=64+j -> xq row j
    for (int i = tid; i < 96 * CC; i += 256) {
        int k = i >> 7, n = i & 127;
        int row = (k < 64) ? (96 + k) : (k - 64);
        sV[i] = xb[row * NN + n0 + n];
    }
    __syncthreads();
    const int tc = tid & 7, tn = tid >> 3;    // tn 0..31
    const int c0 = tc * 8, nb = tn * 4;
    // acc[class-pair p][col q] : classes (c0+2p, c0+2p+1)
    ull acc[4][4];
#pragma unroll
    for (int p = 0; p < 4; p++)
#pragma unroll
        for (int q = 0; q < 4; q++) acc[p][q] = 0ull;
#pragma unroll 2
    for (int k = 0; k < 96; k++) {
        ulonglong2 u01 = *(const ulonglong2*)(sU + k * 64 + c0);      // pairs p=0,1
        ulonglong2 u23 = *(const ulonglong2*)(sU + k * 64 + c0 + 4);  // pairs p=2,3
        float4 v = *(const float4*)(sV + k * 128 + nb);
        ull vp0, vp1, vp2, vp3;
        PACK2(vp0, v.x); PACK2(vp1, v.y); PACK2(vp2, v.z); PACK2(vp3, v.w);
        FMA2(acc[0][0], u01.x, vp0, acc[0][0]); FMA2(acc[0][1], u01.x, vp1, acc[0][1]);
        FMA2(acc[0][2], u01.x, vp2, acc[0][2]); FMA2(acc[0][3], u01.x, vp3, acc[0][3]);
        FMA2(acc[1][0], u01.y, vp0, acc[1][0]); FMA2(acc[1][1], u01.y, vp1, acc[1][1]);
        FMA2(acc[1][2], u01.y, vp2, acc[1][2]); FMA2(acc[1][3], u01.y, vp3, acc[1][3]);
        FMA2(acc[2][0], u23.x, vp0, acc[2][0]); FMA2(acc[2][1], u23.x, vp1, acc[2][1]);
        FMA2(acc[2][2], u23.x, vp2, acc[2][2]); FMA2(acc[2][3], u23.x, vp3, acc[2][3]);
        FMA2(acc[3][0], u23.y, vp0, acc[3][0]); FMA2(acc[3][1], u23.y, vp1, acc[3][1]);
        FMA2(acc[3][2], u23.y, vp2, acc[3][2]); FMA2(acc[3][3], u23.y, vp3, acc[3][3]);
    }
    // unpack: fl[class 0..7][col 0..3]
    float fl[8][4];
#pragma unroll
    for (int p = 0; p < 4; p++)
#pragma unroll
        for (int q = 0; q < 4; q++)
            UNPACK2(fl[2 * p][q], fl[2 * p + 1][q], acc[p][q]);

    float* gl = out + ((size_t)(b * NN + n0)) * 64;
    float* gp = gl + (size_t)BB * NN * 64;
#pragma unroll
    for (int q = 0; q < 4; q++) {
        const size_t col = (size_t)(nb + q) * 64;
        *(float4*)(gl + col + c0)     = make_float4(fl[0][q], fl[1][q], fl[2][q], fl[3][q]);
        *(float4*)(gl + col + c0 + 4) = make_float4(fl[4][q], fl[5][q], fl[6][q], fl[7][q]);
        float m = fl[0][q];
#pragma unroll
        for (int a = 1; a < 8; a++) m = fmaxf(m, fl[a][q]);
#pragma unroll
        for (int off = 1; off < 8; off <<= 1)
            m = fmaxf(m, __shfl_xor_sync(0xffffffffu, m, off));
        float e[8]; float s = 0.f;
#pragma unroll
        for (int a = 0; a < 8; a++) { e[a] = __expf(fl[a][q] - m); s += e[a]; }
#pragma unroll
        for (int off = 1; off < 8; off <<= 1)
            s += __shfl_xor_sync(0xffffffffu, s, off);
        float inv = __frcp_rn(s);
        *(float4*)(gp + col + c0)     = make_float4(e[0] * inv, e[1] * inv, e[2] * inv, e[3] * inv);
        *(float4*)(gp + col + c0 + 4) = make_float4(e[4] * inv, e[5] * inv, e[6] * inv, e[7] * inv);
    }
}

extern "C" void kernel_launch(void* const* d_in, const int* in_sizes, int n_in,
                              void* d_out, int out_size) {
    const float* x     = (const float*)d_in[0];
    const float* alpha = (const float*)d_in[1];
    const float* kp    = (const float*)d_in[2];
    const float* E     = (const float*)d_in[3];
    const float* M     = (const float*)d_in[4];
    float* out = (float*)d_out;

    const int smemB = (4096*2 + 3072 + 2048*4) * 4; // 77,824 B
    const int smemC = (96 * 64 + 96 * 128) * 4;     // 73,728 B
    cudaFuncSetAttribute(kB, cudaFuncAttributeMaxDynamicSharedMemorySize, smemB);
    cudaFuncSetAttribute(kC, cudaFuncAttributeMaxDynamicSharedMemorySize, smemC);

    kZ<<<(BB * 3072 + 255) / 256, 256>>>();
    kA<<<dim3(ACH, BB), 256>>>(x);
    kB<<<BB, 512, smemB>>>(alpha, kp, E, M);
    kC<<<dim3(NN / CC, BB), 256, smemC>>>(x, E, out);
}

// round 12
// speedup vs baseline: 1.0052x; 1.0052x over previous
#include <cuda_runtime.h>

#define BB 16
#define NN 2048
#define NCTX 2047
#define EMB 64
#define DIN 160
#define NLAYERS 3
#define CHN 64
#define ACH 32
#define CC 64

typedef unsigned long long ull;

#define PACK2(d, x)      asm("mov.b64 %0, {%1, %1};" : "=l"(d) : "f"(x))
#define UNPACK2(lo, hi, v) asm("mov.b64 {%0, %1}, %2;" : "=f"(lo), "=f"(hi) : "l"(v))
#define FMA2(d, a, b, c) asm("fma.rn.f32x2 %0, %1, %2, %3;" : "=l"(d) : "l"(a), "l"(b), "l"(c))

// Scratch (allocation-free rule: device globals)
__device__ float g_R[BB * 96 * 32];   // accumulated R per batch
__device__ float g_P[BB * 64 * 32];   // P[c][j] per batch

// ---------------- Kernel Z: zero g_R ----------------
extern "C" __global__ void kZ() {
    int i = blockIdx.x * 256 + threadIdx.x;
    if (i < BB * 3072) g_R[i] = 0.f;
}

// ---------------- Kernel A: R[b] += x[0:96,chunk] @ x[0:32,chunk]^T ----------------
// 8 warps; warp owns 12 rows (6 ull pairs, BROADCAST loads), lane owns 1 q-col.
extern "C" __global__ void __launch_bounds__(256) kA(const float* __restrict__ x) {
    __shared__ float sx[CHN * 98];
    const int b = blockIdx.y, ch = blockIdx.x, tid = threadIdx.x;
    const int wid = tid >> 5, lane = tid & 31;
    const int n0 = ch * CHN;
    const int count = min(CHN, NCTX - n0);
    const float* xb = x + (size_t)b * DIN * NN;
    for (int i = tid; i < 96 * CHN; i += 256) {
        int r = i >> 6, n = i & 63;
        sx[n * 98 + r] = (n < count) ? xb[r * NN + n0 + n] : 0.f;
    }
    __syncthreads();
    const int r0 = wid * 12;
    ull acc[6];
#pragma unroll
    for (int p = 0; p < 6; p++) acc[p] = 0ull;
#pragma unroll 4
    for (int n = 0; n < CHN; n++) {
        const float* row = sx + n * 98;
        // broadcast loads: warp-uniform addresses
        ull a0 = *(const ull*)(row + r0);
        ull a1 = *(const ull*)(row + r0 + 2);
        ull a2 = *(const ull*)(row + r0 + 4);
        ull a3 = *(const ull*)(row + r0 + 6);
        ull a4 = *(const ull*)(row + r0 + 8);
        ull a5 = *(const ull*)(row + r0 + 10);
        float qv = row[lane];            // coalesced, conflict-free (stride 98 % 32 = 2)
        ull q;
        PACK2(q, qv);
        FMA2(acc[0], a0, q, acc[0]);
        FMA2(acc[1], a1, q, acc[1]);
        FMA2(acc[2], a2, q, acc[2]);
        FMA2(acc[3], a3, q, acc[3]);
        FMA2(acc[4], a4, q, acc[4]);
        FMA2(acc[5], a5, q, acc[5]);
    }
    float* rb = g_R + b * 3072;
#pragma unroll
    for (int p = 0; p < 6; p++) {
        float lo, hi;
        UNPACK2(lo, hi, acc[p]);
        atomicAdd(rb + (r0 + 2 * p) * 32 + lane, lo);
        atomicAdd(rb + (r0 + 2 * p + 1) * 32 + lane, hi);
    }
}

// ---------------- Kernel B: per-batch tiny algebra -> P ----------------
extern "C" __global__ void kB(const float* __restrict__ alpha,
                              const float* __restrict__ kp_,
                              const float* __restrict__ E,
                              const float* __restrict__ M) {
    extern __shared__ float smb[];
    float* sE   = smb;           // 4096
    float* sM   = sE + 4096;     // 4096
    float* sR   = sM + 4096;     // 3072  (rows 0..31 = G, rows 32..95 = C)
    float* sW   = sR + 3072;     // 2048
    float* sS   = sW + 2048;     // 2048
    float* sT   = sS + 2048;     // 2048
    float* sSum = sT + 2048;     // 2048
    const int b = blockIdx.x, tid = threadIdx.x; // 512 threads
    for (int i = tid; i < 4096; i += 512) { sE[i] = E[i]; sM[i] = M[i]; }
    for (int i = tid; i < 3072; i += 512) sR[i] = g_R[b * 3072 + i];
    for (int i = tid; i < 2048; i += 512) sSum[i] = 0.f;
    __syncthreads();

    const int i0 = tid >> 3;
    const int j0 = (tid & 7) * 4;
    const float* sC = sR + 32 * 32;

    // W0 = E @ C
    {
        float a0 = 0, a1 = 0, a2 = 0, a3 = 0;
#pragma unroll
        for (int k = 0; k < 64; k++) {
            float e = sE[i0 * 64 + k];
            float4 cv = *(const float4*)(sC + k * 32 + j0);
            a0 += e * cv.x; a1 += e * cv.y; a2 += e * cv.z; a3 += e * cv.w;
        }
        *(float4*)(sW + i0 * 32 + j0) = make_float4(a0, a1, a2, a3);
    }
    __syncthreads();

    const float kp = kp_[0];
    for (int l = 0; l < NLAYERS; l++) {
        float sc = kp * alpha[l * EMB + i0] * (1.0f / (float)NCTX);
        {
            float4 wv = *(const float4*)(sW + i0 * 32 + j0);
            float4 sv = make_float4(sc * wv.x, sc * wv.y, sc * wv.z, sc * wv.w);
            *(float4*)(sS + i0 * 32 + j0) = sv;
            float4 su = *(const float4*)(sSum + i0 * 32 + j0);
            su.x += sv.x; su.y += sv.y; su.z += sv.z; su.w += sv.w;
            *(float4*)(sSum + i0 * 32 + j0) = su;
        }
        __syncthreads();
        if (l < NLAYERS - 1) {
            // T = M @ S
            float a0 = 0, a1 = 0, a2 = 0, a3 = 0;
#pragma unroll
            for (int k = 0; k < 64; k++) {
                float m = sM[i0 * 64 + k];
                float4 sv = *(const float4*)(sS + k * 32 + j0);
                a0 += m * sv.x; a1 += m * sv.y; a2 += m * sv.z; a3 += m * sv.w;
            }
            *(float4*)(sT + i0 * 32 + j0) = make_float4(a0, a1, a2, a3);
            __syncthreads();
            // W += T @ G
            a0 = 0; a1 = 0; a2 = 0; a3 = 0;
#pragma unroll
            for (int p = 0; p < 32; p++) {
                float t = sT[i0 * 32 + p];
                float4 gv = *(const float4*)(sR + p * 32 + j0);
                a0 += t * gv.x; a1 += t * gv.y; a2 += t * gv.z; a3 += t * gv.w;
            }
            float4 wv = *(const float4*)(sW + i0 * 32 + j0);
            wv.x += a0; wv.y += a1; wv.z += a2; wv.w += a3;
            *(float4*)(sW + i0 * 32 + j0) = wv;
            __syncthreads();
        }
    }
    // P[c][j] = sum_d E[d][c] * Sum[d][j]  (c = i0)
    {
        float a0 = 0, a1 = 0, a2 = 0, a3 = 0;
#pragma unroll
        for (int d = 0; d < 64; d++) {
            float e = sE[d * 64 + i0];
            float4 sv = *(const float4*)(sSum + d * 32 + j0);
            a0 += e * sv.x; a1 += e * sv.y; a2 += e * sv.z; a3 += e * sv.w;
        }
        *(float4*)(g_P + (size_t)(b * 64 + i0) * 32 + j0) = make_float4(a0, a1, a2, a3);
    }
}

// ---------------- Kernel C: logits = U^T @ V, broadcast-U f32x2 GEMM + 2-stage softmax ----
// 8 warps; warp owns 8 classes (4 native ull pairs, broadcast LDS), lane owns 2 cols.
extern "C" __global__ void __launch_bounds__(256) kC(const float* __restrict__ x,
                                                     const float* __restrict__ E,
                                                     float* __restrict__ out) {
    extern __shared__ float smc[];
    float* sU   = smc;            // 96*64
    float* sV   = sU + 96 * 64;   // 96*64
    float* redm = sV + 96 * 64;   // 8*66
    float* reds = redm + 8 * 66;  // 8*66
    const int b = blockIdx.y, chn = blockIdx.x, tid = threadIdx.x;
    const int wid = tid >> 5, lane = tid & 31;
    const int n0 = chn * CC;
    const float* xb = x + (size_t)b * DIN * NN;
    // U[k][c]: k<64 -> E[k][c]; k=64+j -> P[c][j]
    for (int i = tid; i < 96 * 64; i += 256) {
        int k = i >> 6, c = i & 63;
        sU[i] = (k < 64) ? E[i] : g_P[(size_t)(b * 64 + c) * 32 + (k - 64)];
    }
    // V[k][n]: k<64 -> f0 row (96+k); k=64+j -> xq row j
    for (int i = tid; i < 96 * CC; i += 256) {
        int k = i >> 6, n = i & 63;
        int row = (k < 64) ? (96 + k) : (k - 64);
        sV[i] = xb[row * NN + n0 + n];
    }
    __syncthreads();
    const int c0 = wid * 8;       // 8 classes per warp (warp-uniform)
    const int nb = lane * 2;      // 2 cols per lane
    ull acc[4][2];
#pragma unroll
    for (int p = 0; p < 4; p++) { acc[p][0] = 0ull; acc[p][1] = 0ull; }
#pragma unroll 4
    for (int k = 0; k < 96; k++) {
        const float* su = sU + k * 64 + c0;
        ulonglong2 u01 = *(const ulonglong2*)(su);      // broadcast (warp-uniform addr)
        ulonglong2 u23 = *(const ulonglong2*)(su + 4);  // broadcast
        float2 v = *(const float2*)(sV + k * 64 + nb);  // coalesced
        ull vp0, vp1;
        PACK2(vp0, v.x); PACK2(vp1, v.y);
        FMA2(acc[0][0], u01.x, vp0, acc[0][0]); FMA2(acc[0][1], u01.x, vp1, acc[0][1]);
        FMA2(acc[1][0], u01.y, vp0, acc[1][0]); FMA2(acc[1][1], u01.y, vp1, acc[1][1]);
        FMA2(acc[2][0], u23.x, vp0, acc[2][0]); FMA2(acc[2][1], u23.x, vp1, acc[2][1]);
        FMA2(acc[3][0], u23.y, vp0, acc[3][0]); FMA2(acc[3][1], u23.y, vp1, acc[3][1]);
    }
    // fl[class 0..7][col 0..1]
    float fl[8][2];
#pragma unroll
    for (int p = 0; p < 4; p++) {
        UNPACK2(fl[2 * p][0], fl[2 * p + 1][0], acc[p][0]);
        UNPACK2(fl[2 * p][1], fl[2 * p + 1][1], acc[p][1]);
    }
    // stage 1: per-warp partial max for each of the lane's 2 cols
    float pm0 = fl[0][0], pm1 = fl[0][1];
#pragma unroll
    for (int a = 1; a < 8; a++) { pm0 = fmaxf(pm0, fl[a][0]); pm1 = fmaxf(pm1, fl[a][1]); }
    *(float2*)(redm + wid * 66 + nb) = make_float2(pm0, pm1);

    // store logits from registers while waiting
    float* gl = out + ((size_t)(b * NN + n0)) * 64;
    float* gp = gl + (size_t)BB * NN * 64;
    {
        const size_t col0 = (size_t)nb * 64, col1 = (size_t)(nb + 1) * 64;
        *(float4*)(gl + col0 + c0)     = make_float4(fl[0][0], fl[1][0], fl[2][0], fl[3][0]);
        *(float4*)(gl + col0 + c0 + 4) = make_float4(fl[4][0], fl[5][0], fl[6][0], fl[7][0]);
        *(float4*)(gl + col1 + c0)     = make_float4(fl[0][1], fl[1][1], fl[2][1], fl[3][1]);
        *(float4*)(gl + col1 + c0 + 4) = make_float4(fl[4][1], fl[5][1], fl[6][1], fl[7][1]);
    }
    __syncthreads();
    float m0 = -1e30f, m1 = -1e30f;
#pragma unroll
    for (int w = 0; w < 8; w++) {
        float2 r = *(const float2*)(redm + w * 66 + nb);
        m0 = fmaxf(m0, r.x); m1 = fmaxf(m1, r.y);
    }
    float e[8][2];
    float s0 = 0.f, s1 = 0.f;
#pragma unroll
    for (int a = 0; a < 8; a++) {
        e[a][0] = __expf(fl[a][0] - m0); s0 += e[a][0];
        e[a][1] = __expf(fl[a][1] - m1); s1 += e[a][1];
    }
    *(float2*)(reds + wid * 66 + nb) = make_float2(s0, s1);
    __syncthreads();
    float t0 = 0.f, t1 = 0.f;
#pragma unroll
    for (int w = 0; w < 8; w++) {
        float2 r = *(const float2*)(reds + w * 66 + nb);
        t0 += r.x; t1 += r.y;
    }
    float inv0 = __frcp_rn(t0), inv1 = __frcp_rn(t1);
    {
        const size_t col0 = (size_t)nb * 64, col1 = (size_t)(nb + 1) * 64;
        *(float4*)(gp + col0 + c0)     = make_float4(e[0][0] * inv0, e[1][0] * inv0, e[2][0] * inv0, e[3][0] * inv0);
        *(float4*)(gp + col0 + c0 + 4) = make_float4(e[4][0] * inv0, e[5][0] * inv0, e[6][0] * inv0, e[7][0] * inv0);
        *(float4*)(gp + col1 + c0)     = make_float4(e[0][1] * inv1, e[1][1] * inv1, e[2][1] * inv1, e[3][1] * inv1);
        *(float4*)(gp + col1 + c0 + 4) = make_float4(e[4][1] * inv1, e[5][1] * inv1, e[6][1] * inv1, e[7][1] * inv1);
    }
}

extern "C" void kernel_launch(void* const* d_in, const int* in_sizes, int n_in,
                              void* d_out, int out_size) {
    const float* x     = (const float*)d_in[0];
    const float* alpha = (const float*)d_in[1];
    const float* kp    = (const float*)d_in[2];
    const float* E     = (const float*)d_in[3];
    const float* M     = (const float*)d_in[4];
    float* out = (float*)d_out;

    const int smemB = (4096*2 + 3072 + 2048*4) * 4;          // 77,824 B
    const int smemC = (96 * 64 * 2 + 2 * 8 * 66) * 4;        // 53,376 B
    cudaFuncSetAttribute(kB, cudaFuncAttributeMaxDynamicSharedMemorySize, smemB);
    cudaFuncSetAttribute(kC, cudaFuncAttributeMaxDynamicSharedMemorySize, smemC);

    kZ<<<(BB * 3072 + 255) / 256, 256>>>();
    kA<<<dim3(ACH, BB), 256>>>(x);
    kB<<<BB, 512, smemB>>>(alpha, kp, E, M);
    kC<<<dim3(NN / CC, BB), 256, smemC>>>(x, E, out);
}

// round 13
// speedup vs baseline: 1.0788x; 1.0733x over previous
#include <cuda_runtime.h>

#define BB 16
#define NN 2048
#define NCTX 2047
#define EMB 64
#define DIN 160
#define NLAYERS 3
#define CHN 128
#define ACH 16
#define CC 64

typedef unsigned long long ull;

#define PACK2(d, x)      asm("mov.b64 %0, {%1, %1};" : "=l"(d) : "f"(x))
#define UNPACK2(lo, hi, v) asm("mov.b64 {%0, %1}, %2;" : "=f"(lo), "=f"(hi) : "l"(v))
#define FMA2(d, a, b, c) asm("fma.rn.f32x2 %0, %1, %2, %3;" : "=l"(d) : "l"(a), "l"(b), "l"(c))

// Scratch (allocation-free rule: device globals)
__device__ float g_Rpart[BB * ACH * 96 * 32];   // per-(batch,chunk) partial R
__device__ float g_R[BB * 96 * 32];             // reduced R per batch
__device__ float g_P[BB * 64 * 32];             // P[c][j] per batch

// ---------------- Kernel A: Rpart = x[0:96,chunk] @ x[0:32,chunk]^T (pipelined) ------
// 256 threads, transposed tile sx[n][96] stride 98, 3 row-pairs x 2 cols per thread.
extern "C" __global__ void __launch_bounds__(256) kA(const float* __restrict__ x) {
    extern __shared__ float sx[]; // [CHN][98]
    const int b = blockIdx.y, ch = blockIdx.x, tid = threadIdx.x;
    const int n0 = ch * CHN;
    const int count = min(CHN, NCTX - n0);
    const float* xb = x + (size_t)b * DIN * NN;
    for (int i = tid; i < 96 * CHN; i += 256) {
        int r = i >> 7, n = i & 127;
        sx[n * 98 + r] = (n < count) ? xb[r * NN + n0 + n] : 0.f;
    }
    __syncthreads();
    const int tc = tid & 15, tr = tid >> 4;   // tr 0..15
    const int r0 = tr * 6, j0 = tc * 2;
    ull acc[3][2];
#pragma unroll
    for (int p = 0; p < 3; p++) { acc[p][0] = 0ull; acc[p][1] = 0ull; }

    const float* row = sx + r0;
    const float* qrow = sx + j0;
    // prefetch n = 0
    ull a0 = *(const ull*)(row);
    ull a1 = *(const ull*)(row + 2);
    ull a2 = *(const ull*)(row + 4);
    float2 q = *(const float2*)(qrow);
#pragma unroll 4
    for (int n = 0; n < CHN - 1; n++) {
        const float* rn = row + (n + 1) * 98;
        const float* qn = qrow + (n + 1) * 98;
        ull b0 = *(const ull*)(rn);
        ull b1 = *(const ull*)(rn + 2);
        ull b2 = *(const ull*)(rn + 4);
        float2 q2 = *(const float2*)(qn);
        ull q0, q1;
        PACK2(q0, q.x); PACK2(q1, q.y);
        FMA2(acc[0][0], a0, q0, acc[0][0]); FMA2(acc[0][1], a0, q1, acc[0][1]);
        FMA2(acc[1][0], a1, q0, acc[1][0]); FMA2(acc[1][1], a1, q1, acc[1][1]);
        FMA2(acc[2][0], a2, q0, acc[2][0]); FMA2(acc[2][1], a2, q1, acc[2][1]);
        a0 = b0; a1 = b1; a2 = b2; q = q2;
    }
    {   // last iteration
        ull q0, q1;
        PACK2(q0, q.x); PACK2(q1, q.y);
        FMA2(acc[0][0], a0, q0, acc[0][0]); FMA2(acc[0][1], a0, q1, acc[0][1]);
        FMA2(acc[1][0], a1, q0, acc[1][0]); FMA2(acc[1][1], a1, q1, acc[1][1]);
        FMA2(acc[2][0], a2, q0, acc[2][0]); FMA2(acc[2][1], a2, q1, acc[2][1]);
    }
    float* outp = g_Rpart + (size_t)(b * ACH + ch) * 3072;
#pragma unroll
    for (int p = 0; p < 3; p++) {
        float l0, h0, l1, h1;
        UNPACK2(l0, h0, acc[p][0]);
        UNPACK2(l1, h1, acc[p][1]);
        *(float2*)(outp + (r0 + 2 * p) * 32 + j0)     = make_float2(l0, l1);
        *(float2*)(outp + (r0 + 2 * p + 1) * 32 + j0) = make_float2(h0, h1);
    }
}

// ---------------- Kernel R: reduce ACH partials -> g_R ----------------
extern "C" __global__ void kR() {
    const int b = blockIdx.x;
    const int e = blockIdx.y * 256 + threadIdx.x;   // 0..3071
    const float* p = g_Rpart + (size_t)b * ACH * 3072 + e;
    float s = 0.f;
#pragma unroll
    for (int c = 0; c < ACH; c++) s += p[c * 3072];
    g_R[b * 3072 + e] = s;
}

// ---------------- Kernel B: per-batch tiny algebra -> P ----------------
extern "C" __global__ void kB(const float* __restrict__ alpha,
                              const float* __restrict__ kp_,
                              const float* __restrict__ E,
                              const float* __restrict__ M) {
    extern __shared__ float smb[];
    float* sE   = smb;           // 4096
    float* sM   = sE + 4096;     // 4096
    float* sR   = sM + 4096;     // 3072  (rows 0..31 = G, rows 32..95 = C)
    float* sW   = sR + 3072;     // 2048
    float* sS   = sW + 2048;     // 2048
    float* sT   = sS + 2048;     // 2048
    float* sSum = sT + 2048;     // 2048
    const int b = blockIdx.x, tid = threadIdx.x; // 512 threads
    for (int i = tid; i < 4096; i += 512) { sE[i] = E[i]; sM[i] = M[i]; }
    for (int i = tid; i < 3072; i += 512) sR[i] = g_R[b * 3072 + i];
    for (int i = tid; i < 2048; i += 512) sSum[i] = 0.f;
    __syncthreads();

    const int i0 = tid >> 3;
    const int j0 = (tid & 7) * 4;
    const float* sC = sR + 32 * 32;

    // W0 = E @ C
    {
        float a0 = 0, a1 = 0, a2 = 0, a3 = 0;
#pragma unroll
        for (int k = 0; k < 64; k++) {
            float e = sE[i0 * 64 + k];
            float4 cv = *(const float4*)(sC + k * 32 + j0);
            a0 += e * cv.x; a1 += e * cv.y; a2 += e * cv.z; a3 += e * cv.w;
        }
        *(float4*)(sW + i0 * 32 + j0) = make_float4(a0, a1, a2, a3);
    }
    __syncthreads();

    const float kp = kp_[0];
    for (int l = 0; l < NLAYERS; l++) {
        float sc = kp * alpha[l * EMB + i0] * (1.0f / (float)NCTX);
        {
            float4 wv = *(const float4*)(sW + i0 * 32 + j0);
            float4 sv = make_float4(sc * wv.x, sc * wv.y, sc * wv.z, sc * wv.w);
            *(float4*)(sS + i0 * 32 + j0) = sv;
            float4 su = *(const float4*)(sSum + i0 * 32 + j0);
            su.x += sv.x; su.y += sv.y; su.z += sv.z; su.w += sv.w;
            *(float4*)(sSum + i0 * 32 + j0) = su;
        }
        __syncthreads();
        if (l < NLAYERS - 1) {
            // T = M @ S
            float a0 = 0, a1 = 0, a2 = 0, a3 = 0;
#pragma unroll
            for (int k = 0; k < 64; k++) {
                float m = sM[i0 * 64 + k];
                float4 sv = *(const float4*)(sS + k * 32 + j0);
                a0 += m * sv.x; a1 += m * sv.y; a2 += m * sv.z; a3 += m * sv.w;
            }
            *(float4*)(sT + i0 * 32 + j0) = make_float4(a0, a1, a2, a3);
            __syncthreads();
            // W += T @ G
            a0 = 0; a1 = 0; a2 = 0; a3 = 0;
#pragma unroll
            for (int p = 0; p < 32; p++) {
                float t = sT[i0 * 32 + p];
                float4 gv = *(const float4*)(sR + p * 32 + j0);
                a0 += t * gv.x; a1 += t * gv.y; a2 += t * gv.z; a3 += t * gv.w;
            }
            float4 wv = *(const float4*)(sW + i0 * 32 + j0);
            wv.x += a0; wv.y += a1; wv.z += a2; wv.w += a3;
            *(float4*)(sW + i0 * 32 + j0) = wv;
            __syncthreads();
        }
    }
    // P[c][j] = sum_d E[d][c] * Sum[d][j]  (c = i0)
    {
        float a0 = 0, a1 = 0, a2 = 0, a3 = 0;
#pragma unroll
        for (int d = 0; d < 64; d++) {
            float e = sE[d * 64 + i0];
            float4 sv = *(const float4*)(sSum + d * 32 + j0);
            a0 += e * sv.x; a1 += e * sv.y; a2 += e * sv.z; a3 += e * sv.w;
        }
        *(float4*)(g_P + (size_t)(b * 64 + i0) * 32 + j0) = make_float4(a0, a1, a2, a3);
    }
}

// ---------------- Kernel C: logits = U^T @ V (pipelined f32x2), softmax, direct stores ----
// CC=64 cols/CTA (grid 512), 256 threads, 4 classes x 4 cols per thread, prefetched.
extern "C" __global__ void __launch_bounds__(256, 4) kC(const float* __restrict__ x,
                                                        const float* __restrict__ E,
                                                        float* __restrict__ out) {
    extern __shared__ float smc[];
    float* sU = smc;            // 96 x 64
    float* sV = sU + 96 * 64;   // 96 x 64
    const int b = blockIdx.y, chn = blockIdx.x, tid = threadIdx.x;
    const int n0 = chn * CC;
    const float* xb = x + (size_t)b * DIN * NN;
    // U[k][c]: k<64 -> E[k][c]; k=64+j -> P[c][j]
    for (int i = tid; i < 96 * 64; i += 256) {
        int k = i >> 6, c = i & 63;
        sU[i] = (k < 64) ? E[i] : g_P[(size_t)(b * 64 + c) * 32 + (k - 64)];
    }
    // V[k][n]: k<64 -> f0 row (96+k); k=64+j -> xq row j
    for (int i = tid; i < 96 * CC; i += 256) {
        int k = i >> 6, n = i & 63;
        int row = (k < 64) ? (96 + k) : (k - 64);
        sV[i] = xb[row * NN + n0 + n];
    }
    __syncthreads();
    const int tc = tid & 15, tn = tid >> 4;   // tn 0..15
    const int c0 = tc * 4, nb = tn * 4;
    ull acc[4][2];
#pragma unroll
    for (int a = 0; a < 4; a++) { acc[a][0] = 0ull; acc[a][1] = 0ull; }

    const float* pu = sU + c0;
    const float* pv = sV + nb;
    float4 u = *(const float4*)(pu);
    ulonglong2 v = *(const ulonglong2*)(pv);
#pragma unroll 4
    for (int k = 0; k < 95; k++) {
        float4 u2 = *(const float4*)(pu + (k + 1) * 64);
        ulonglong2 v2 = *(const ulonglong2*)(pv + (k + 1) * 64);
        ull ad0, ad1, ad2, ad3;
        PACK2(ad0, u.x); PACK2(ad1, u.y); PACK2(ad2, u.z); PACK2(ad3, u.w);
        FMA2(acc[0][0], ad0, v.x, acc[0][0]); FMA2(acc[0][1], ad0, v.y, acc[0][1]);
        FMA2(acc[1][0], ad1, v.x, acc[1][0]); FMA2(acc[1][1], ad1, v.y, acc[1][1]);
        FMA2(acc[2][0], ad2, v.x, acc[2][0]); FMA2(acc[2][1], ad2, v.y, acc[2][1]);
        FMA2(acc[3][0], ad3, v.x, acc[3][0]); FMA2(acc[3][1], ad3, v.y, acc[3][1]);
        u = u2; v = v2;
    }
    {   // k = 95
        ull ad0, ad1, ad2, ad3;
        PACK2(ad0, u.x); PACK2(ad1, u.y); PACK2(ad2, u.z); PACK2(ad3, u.w);
        FMA2(acc[0][0], ad0, v.x, acc[0][0]); FMA2(acc[0][1], ad0, v.y, acc[0][1]);
        FMA2(acc[1][0], ad1, v.x, acc[1][0]); FMA2(acc[1][1], ad1, v.y, acc[1][1]);
        FMA2(acc[2][0], ad2, v.x, acc[2][0]); FMA2(acc[2][1], ad2, v.y, acc[2][1]);
        FMA2(acc[3][0], ad3, v.x, acc[3][0]); FMA2(acc[3][1], ad3, v.y, acc[3][1]);
    }
    // unpack: fl[class 0..3][col 0..3]
    float fl[4][4];
#pragma unroll
    for (int a = 0; a < 4; a++) {
        UNPACK2(fl[a][0], fl[a][1], acc[a][0]);
        UNPACK2(fl[a][2], fl[a][3], acc[a][1]);
    }

    float* gl = out + ((size_t)(b * NN + n0)) * 64;
    float* gp = gl + (size_t)BB * NN * 64;
#pragma unroll
    for (int q = 0; q < 4; q++) {
        const size_t col = (size_t)(nb + q) * 64;
        *(float4*)(gl + col + c0) = make_float4(fl[0][q], fl[1][q], fl[2][q], fl[3][q]);
        float m = fmaxf(fmaxf(fl[0][q], fl[1][q]), fmaxf(fl[2][q], fl[3][q]));
#pragma unroll
        for (int off = 1; off < 16; off <<= 1)
            m = fmaxf(m, __shfl_xor_sync(0xffffffffu, m, off));
        float e0 = __expf(fl[0][q] - m);
        float e1 = __expf(fl[1][q] - m);
        float e2 = __expf(fl[2][q] - m);
        float e3 = __expf(fl[3][q] - m);
        float s = e0 + e1 + e2 + e3;
#pragma unroll
        for (int off = 1; off < 16; off <<= 1)
            s += __shfl_xor_sync(0xffffffffu, s, off);
        float inv = __frcp_rn(s);
        *(float4*)(gp + col + c0) = make_float4(e0 * inv, e1 * inv, e2 * inv, e3 * inv);
    }
}

extern "C" void kernel_launch(void* const* d_in, const int* in_sizes, int n_in,
                              void* d_out, int out_size) {
    const float* x     = (const float*)d_in[0];
    const float* alpha = (const float*)d_in[1];
    const float* kp    = (const float*)d_in[2];
    const float* E     = (const float*)d_in[3];
    const float* M     = (const float*)d_in[4];
    float* out = (float*)d_out;

    const int smemA = CHN * 98 * 4;                 // 50,176 B
    const int smemB = (4096*2 + 3072 + 2048*4) * 4; // 77,824 B
    const int smemC = (96 * 64 * 2) * 4;            // 49,152 B
    cudaFuncSetAttribute(kA, cudaFuncAttributeMaxDynamicSharedMemorySize, smemA);
    cudaFuncSetAttribute(kB, cudaFuncAttributeMaxDynamicSharedMemorySize, smemB);
    cudaFuncSetAttribute(kC, cudaFuncAttributeMaxDynamicSharedMemorySize, smemC);

    kA<<<dim3(ACH, BB), 256, smemA>>>(x);
    kR<<<dim3(BB, 12), 256>>>();
    kB<<<BB, 512, smemB>>>(alpha, kp, E, M);
    kC<<<dim3(NN / CC, BB), 256, smemC>>>(x, E, out);
}